// round 1
// baseline (speedup 1.0000x reference)
#include <cuda_runtime.h>
#include <cstddef>

// Problem constants
#define NTOK 8192   // N
#define BB   32     // batch
#define GD   256    // GRU_DIM
#define HD   512    // HAN_DIM
#define ID   128    // INNER_DIM
#define JB   16     // j-rows per block

// Shared-memory strides (floats). Chosen for 16B alignment + conflict-free LDS.128.
#define ESTR   516  // edges row stride (512 + 4)
#define WK_STR 68   // Wk chunk row stride (64 + 4): lane-row mapping -> 4*l bank pattern
#define KSTR   132  // K tile row stride (128 + 4)
#define MSTR   264  // M tile row stride (256 + 8)
#define WQ_STR 260  // Wq chunk row stride (256 + 4)

// Float offsets into dynamic smem
#define OFF_EDGES 0
#define OFF_W     (JB * ESTR)                    // 8256
#define OFF_K     (OFF_W + ID * WK_STR)          // 8256 + 8704 = 16960  (Wq chunk 32*260=8320 fits too)
#define OFF_M     (OFF_K + JB * KSTR)            // + 2112 = 19072
#define OFF_SIM   (OFF_M + JB * MSTR)            // + 4224 = 23296
#define SMEM_FLOATS (OFF_SIM + BB * 17)          // + 544  = 23840
#define SMEM_BYTES  (SMEM_FLOATS * 4)            // 95360 B -> 2 blocks/SM

__global__ __launch_bounds__(256, 2)
void cal_sim_fused_kernel(const float* __restrict__ chg,       // [B, N, GD]
                          const float* __restrict__ edg,       // [N, HD]
                          const unsigned int* __restrict__ maskw, // [B, N] unknown dtype
                          const float* __restrict__ Wq,        // [ID, GD]
                          const float* __restrict__ Wk,        // [ID, HD]
                          float* __restrict__ out)             // [N, B]
{
    extern __shared__ float smf[];
    float* s_edges = smf + OFF_EDGES;
    float* s_w     = smf + OFF_W;      // union: Wk chunk [128][68] / Wq chunk [32][260]
    float* s_K     = smf + OFF_K;      // [16][132]
    float* s_M     = smf + OFF_M;      // [16][264]
    float* s_sim   = smf + OFF_SIM;    // [32][17]  (b-major)

    const int t    = threadIdx.x;
    const int lane = t & 31;
    const int warp = t >> 5;
    const int j0   = blockIdx.x * JB;

    // ---------------- load edges tile [16][512] ----------------
#pragma unroll
    for (int i = 0; i < 8; i++) {
        int idx = t + i * 256;              // 0..2047 float4 slots
        int j   = idx >> 7;                 // /128
        int d4  = idx & 127;
        float4 v = *reinterpret_cast<const float4*>(edg + (size_t)(j0 + j) * HD + 4 * d4);
        *reinterpret_cast<float4*>(s_edges + j * ESTR + 4 * d4) = v;
    }
    // first __syncthreads inside the K loop publishes s_edges

    // ---------------- K[16][128] = edges_tile @ Wk^T (contract d=512) ----------------
    // thread -> outputs: j in {2*warp, 2*warp+1}, e in {lane + 32k, k=0..3}
    float acc0[4] = {0.f, 0.f, 0.f, 0.f};
    float acc1[4] = {0.f, 0.f, 0.f, 0.f};
    const int jr0 = warp * 2, jr1 = jr0 + 1;

    for (int dc = 0; dc < HD; dc += 64) {
        // stage Wk[:, dc:dc+64] -> s_w[128][68]
#pragma unroll
        for (int i = 0; i < 8; i++) {
            int idx = t + i * 256;          // 0..2047 float4 slots
            int e   = idx >> 4;             // /16
            int d4  = idx & 15;
            float4 v = *reinterpret_cast<const float4*>(Wk + (size_t)e * HD + dc + 4 * d4);
            *reinterpret_cast<float4*>(s_w + e * WK_STR + 4 * d4) = v;
        }
        __syncthreads();
#pragma unroll
        for (int d4 = 0; d4 < 16; d4++) {
            float4 a0 = *reinterpret_cast<const float4*>(s_edges + jr0 * ESTR + dc + 4 * d4);
            float4 a1 = *reinterpret_cast<const float4*>(s_edges + jr1 * ESTR + dc + 4 * d4);
#pragma unroll
            for (int k = 0; k < 4; k++) {
                float4 w = *reinterpret_cast<const float4*>(s_w + (lane + 32 * k) * WK_STR + 4 * d4);
                acc0[k] += a0.x * w.x + a0.y * w.y + a0.z * w.z + a0.w * w.w;
                acc1[k] += a1.x * w.x + a1.y * w.y + a1.z * w.z + a1.w * w.w;
            }
        }
        __syncthreads();
    }
#pragma unroll
    for (int k = 0; k < 4; k++) {
        s_K[jr0 * KSTR + lane + 32 * k] = acc0[k];
        s_K[jr1 * KSTR + lane + 32 * k] = acc1[k];
    }

    // ---------------- M[16][256] = K_tile @ Wq (contract e=128), scaled ----------------
    // thread -> outputs: j in {4*tg .. 4*tg+3}, d in {4*td .. 4*td+3}
    float macc[4][4];
#pragma unroll
    for (int a = 0; a < 4; a++)
#pragma unroll
        for (int b = 0; b < 4; b++) macc[a][b] = 0.f;

    const int td = t & 63;
    const int tg = t >> 6;

    for (int ec = 0; ec < ID; ec += 32) {
        // stage Wq[ec:ec+32][256] -> s_w[32][260]
#pragma unroll
        for (int i = 0; i < 8; i++) {
            int idx = t + i * 256;          // 0..2047 float4 slots
            int e   = idx >> 6;             // /64
            int d4  = idx & 63;
            float4 v = *reinterpret_cast<const float4*>(Wq + (size_t)(ec + e) * GD + 4 * d4);
            *reinterpret_cast<float4*>(s_w + e * WQ_STR + 4 * d4) = v;
        }
        __syncthreads();                    // also publishes s_K on first iteration
#pragma unroll
        for (int el = 0; el < 32; el++) {
            float4 w = *reinterpret_cast<const float4*>(s_w + el * WQ_STR + 4 * td);
            float k0 = s_K[(tg * 4 + 0) * KSTR + ec + el];  // warp-broadcast
            float k1 = s_K[(tg * 4 + 1) * KSTR + ec + el];
            float k2 = s_K[(tg * 4 + 2) * KSTR + ec + el];
            float k3 = s_K[(tg * 4 + 3) * KSTR + ec + el];
            macc[0][0] += k0 * w.x; macc[0][1] += k0 * w.y; macc[0][2] += k0 * w.z; macc[0][3] += k0 * w.w;
            macc[1][0] += k1 * w.x; macc[1][1] += k1 * w.y; macc[1][2] += k1 * w.z; macc[1][3] += k1 * w.w;
            macc[2][0] += k2 * w.x; macc[2][1] += k2 * w.y; macc[2][2] += k2 * w.z; macc[2][3] += k2 * w.w;
            macc[3][0] += k3 * w.x; macc[3][1] += k3 * w.y; macc[3][2] += k3 * w.z; macc[3][3] += k3 * w.w;
        }
        __syncthreads();
    }

    const float SCALE = 0.08838834764831845f;  // 128^-0.5
#pragma unroll
    for (int jj = 0; jj < 4; jj++) {
        float4 v = make_float4(macc[jj][0] * SCALE, macc[jj][1] * SCALE,
                               macc[jj][2] * SCALE, macc[jj][3] * SCALE);
        *reinterpret_cast<float4*>(s_M + (tg * 4 + jj) * MSTR + 4 * td) = v;
    }
    __syncthreads();

    // ---------------- sim[b][j] = change[b, j0+j, :] . M[j, :]  (DRAM-bound) ----------------
#pragma unroll 2
    for (int p = warp; p < BB * JB; p += 8) {
        int b  = p >> 4;
        int jr = p & 15;
        const float4* c = reinterpret_cast<const float4*>(chg + ((size_t)b * NTOK + j0 + jr) * GD);
        float4 c0 = c[2 * lane];
        float4 c1 = c[2 * lane + 1];
        const float4* mrow = reinterpret_cast<const float4*>(s_M + jr * MSTR);
        float4 m0 = mrow[2 * lane];
        float4 m1 = mrow[2 * lane + 1];
        float part = c0.x * m0.x + c0.y * m0.y + c0.z * m0.z + c0.w * m0.w
                   + c1.x * m1.x + c1.y * m1.y + c1.z * m1.z + c1.w * m1.w;
#pragma unroll
        for (int s = 16; s; s >>= 1) part += __shfl_xor_sync(0xffffffffu, part, s);
        if (lane == 0) s_sim[b * 17 + jr] = part;
    }
    __syncthreads();

    // ---------------- masked softmax over b (lane == b) ----------------
    // Probe mask dtype from the first 1 KB (bool may arrive as u8 / i32 / f32).
    bool notint = false, notfloat = false;
    for (int i = lane; i < 256; i += 32) {
        unsigned int w = maskw[i];
        notint   |= (w > 1u);
        notfloat |= (w != 0u && w != 0x3f800000u);
    }
    notint   = __any_sync(0xffffffffu, notint);
    notfloat = __any_sync(0xffffffffu, notfloat);
    const int mode = notint ? (notfloat ? 1 : 2) : 0;   // 0=int32, 1=byte, 2=float32

    for (int jr = warp; jr < JB; jr += 8) {
        int jg = j0 + jr;
        float v = s_sim[lane * 17 + jr];
        bool mk;
        if (mode == 0)      mk = reinterpret_cast<const int*>(maskw)[(size_t)lane * NTOK + jg] != 0;
        else if (mode == 1) mk = reinterpret_cast<const unsigned char*>(maskw)[(size_t)lane * NTOK + jg] != 0;
        else                mk = reinterpret_cast<const float*>(maskw)[(size_t)lane * NTOK + jg] != 0.0f;
        v = mk ? v : -1e9f;
        float mx = v;
#pragma unroll
        for (int s = 16; s; s >>= 1) mx = fmaxf(mx, __shfl_xor_sync(0xffffffffu, mx, s));
        float ev = expf(v - mx);
        float sum = ev;
#pragma unroll
        for (int s = 16; s; s >>= 1) sum += __shfl_xor_sync(0xffffffffu, sum, s);
        out[(size_t)jg * BB + lane] = ev / sum;
    }
}

extern "C" void kernel_launch(void* const* d_in, const int* in_sizes, int n_in,
                              void* d_out, int out_size)
{
    const float*        chg  = (const float*)d_in[0];        // change_embeddings [B,N,256]
    const float*        edg  = (const float*)d_in[1];        // edges_embeddings  [N,512]
    const unsigned int* mask = (const unsigned int*)d_in[2]; // mask [B,N] (dtype probed on device)
    const float*        Wq   = (const float*)d_in[3];        // [128,256]
    const float*        Wk   = (const float*)d_in[4];        // [128,512]
    float*              out  = (float*)d_out;                // [N,B]

    cudaFuncSetAttribute(cal_sim_fused_kernel,
                         cudaFuncAttributeMaxDynamicSharedMemorySize, SMEM_BYTES);
    cal_sim_fused_kernel<<<NTOK / JB, 256, SMEM_BYTES>>>(chg, edg, mask, Wq, Wk, out);
}

// round 2
// speedup vs baseline: 1.2776x; 1.2776x over previous
#include <cuda_runtime.h>
#include <cstddef>

// Problem constants
#define NTOK 8192   // N
#define BB   32     // batch
#define GD   256    // GRU_DIM
#define HD   512    // HAN_DIM
#define ID   128    // INNER_DIM

// ======================= Kernel A: M = scale * (edges @ Wk^T) @ Wq =======================
#define JB 16       // j-rows per block (kernel A)

// Shared-memory strides (floats)
#define ESTR   516  // edges row stride (512 + 4)
#define WK_STR 68   // Wk chunk row stride (64 + 4)
#define KSTR   132  // K tile row stride (128 + 4)
#define WQ_STR 260  // Wq chunk row stride (256 + 4)

#define OFF_EDGES 0
#define OFF_W     (JB * ESTR)                    // 8256
#define OFF_K     (OFF_W + ID * WK_STR)          // 16960
#define A_SMEM_FLOATS (OFF_K + JB * KSTR)        // 19072
#define A_SMEM_BYTES  (A_SMEM_FLOATS * 4)        // 76288 B -> 2 blocks/SM

// 8 MB scratch for M [N, 256]
__device__ float g_M[NTOK * GD];

__global__ __launch_bounds__(256, 2)
void cal_sim_gemm_kernel(const float* __restrict__ edg,       // [N, HD]
                         const float* __restrict__ Wq,        // [ID, GD]
                         const float* __restrict__ Wk)        // [ID, HD]
{
    extern __shared__ float smf[];
    float* s_edges = smf + OFF_EDGES;
    float* s_w     = smf + OFF_W;      // union: Wk chunk [128][68] / Wq chunk [32][260]
    float* s_K     = smf + OFF_K;      // [16][132]

    const int t    = threadIdx.x;
    const int lane = t & 31;
    const int warp = t >> 5;
    const int j0   = blockIdx.x * JB;

    // ---- load edges tile [16][512] ----
#pragma unroll
    for (int i = 0; i < 8; i++) {
        int idx = t + i * 256;
        int j   = idx >> 7;
        int d4  = idx & 127;
        float4 v = *reinterpret_cast<const float4*>(edg + (size_t)(j0 + j) * HD + 4 * d4);
        *reinterpret_cast<float4*>(s_edges + j * ESTR + 4 * d4) = v;
    }

    // ---- K[16][128] = edges_tile @ Wk^T ----
    float acc0[4] = {0.f, 0.f, 0.f, 0.f};
    float acc1[4] = {0.f, 0.f, 0.f, 0.f};
    const int jr0 = warp * 2, jr1 = jr0 + 1;

    for (int dc = 0; dc < HD; dc += 64) {
#pragma unroll
        for (int i = 0; i < 8; i++) {
            int idx = t + i * 256;
            int e   = idx >> 4;
            int d4  = idx & 15;
            float4 v = *reinterpret_cast<const float4*>(Wk + (size_t)e * HD + dc + 4 * d4);
            *reinterpret_cast<float4*>(s_w + e * WK_STR + 4 * d4) = v;
        }
        __syncthreads();
#pragma unroll
        for (int d4 = 0; d4 < 16; d4++) {
            float4 a0 = *reinterpret_cast<const float4*>(s_edges + jr0 * ESTR + dc + 4 * d4);
            float4 a1 = *reinterpret_cast<const float4*>(s_edges + jr1 * ESTR + dc + 4 * d4);
#pragma unroll
            for (int k = 0; k < 4; k++) {
                float4 w = *reinterpret_cast<const float4*>(s_w + (lane + 32 * k) * WK_STR + 4 * d4);
                acc0[k] += a0.x * w.x + a0.y * w.y + a0.z * w.z + a0.w * w.w;
                acc1[k] += a1.x * w.x + a1.y * w.y + a1.z * w.z + a1.w * w.w;
            }
        }
        __syncthreads();
    }
#pragma unroll
    for (int k = 0; k < 4; k++) {
        s_K[jr0 * KSTR + lane + 32 * k] = acc0[k];
        s_K[jr1 * KSTR + lane + 32 * k] = acc1[k];
    }

    // ---- M[16][256] = K_tile @ Wq, scaled; write to g_M ----
    float macc[4][4];
#pragma unroll
    for (int a = 0; a < 4; a++)
#pragma unroll
        for (int b = 0; b < 4; b++) macc[a][b] = 0.f;

    const int td = t & 63;
    const int tg = t >> 6;

    for (int ec = 0; ec < ID; ec += 32) {
#pragma unroll
        for (int i = 0; i < 8; i++) {
            int idx = t + i * 256;
            int e   = idx >> 6;
            int d4  = idx & 63;
            float4 v = *reinterpret_cast<const float4*>(Wq + (size_t)(ec + e) * GD + 4 * d4);
            *reinterpret_cast<float4*>(s_w + e * WQ_STR + 4 * d4) = v;
        }
        __syncthreads();                    // also publishes s_K on first iteration
#pragma unroll
        for (int el = 0; el < 32; el++) {
            float4 w = *reinterpret_cast<const float4*>(s_w + el * WQ_STR + 4 * td);
            float k0 = s_K[(tg * 4 + 0) * KSTR + ec + el];
            float k1 = s_K[(tg * 4 + 1) * KSTR + ec + el];
            float k2 = s_K[(tg * 4 + 2) * KSTR + ec + el];
            float k3 = s_K[(tg * 4 + 3) * KSTR + ec + el];
            macc[0][0] += k0 * w.x; macc[0][1] += k0 * w.y; macc[0][2] += k0 * w.z; macc[0][3] += k0 * w.w;
            macc[1][0] += k1 * w.x; macc[1][1] += k1 * w.y; macc[1][2] += k1 * w.z; macc[1][3] += k1 * w.w;
            macc[2][0] += k2 * w.x; macc[2][1] += k2 * w.y; macc[2][2] += k2 * w.z; macc[2][3] += k2 * w.w;
            macc[3][0] += k3 * w.x; macc[3][1] += k3 * w.y; macc[3][2] += k3 * w.z; macc[3][3] += k3 * w.w;
        }
        __syncthreads();
    }

    const float SCALE = 0.08838834764831845f;  // 128^-0.5
#pragma unroll
    for (int jj = 0; jj < 4; jj++) {
        float4 v = make_float4(macc[jj][0] * SCALE, macc[jj][1] * SCALE,
                               macc[jj][2] * SCALE, macc[jj][3] * SCALE);
        *reinterpret_cast<float4*>(g_M + (size_t)(j0 + tg * 4 + jj) * GD + 4 * td) = v;
    }
}

// ======================= Kernel B: sim + masked softmax over b =======================
#define JB2 8       // j-rows per block (kernel B); grid = 1024

__global__ __launch_bounds__(256)
void cal_sim_stream_kernel(const float* __restrict__ chg,          // [B, N, GD]
                           const unsigned int* __restrict__ maskw, // [B, N] dtype probed
                           float* __restrict__ out)                // [N, B]
{
    __shared__ float s_M[JB2 * GD];     // 8 KB, row j: 256 floats contiguous
    __shared__ float s_sim[BB * 9];     // b-major, stride 9

    const int t    = threadIdx.x;
    const int lane = t & 31;
    const int warp = t >> 5;            // 0..7 == jr
    const int j0   = blockIdx.x * JB2;

    // load M tile: 2048 floats = 512 float4, 256 threads x 2
#pragma unroll
    for (int i = 0; i < 2; i++) {
        int idx = t + i * 256;
        *reinterpret_cast<float4*>(s_M + 4 * idx) =
            *reinterpret_cast<const float4*>(g_M + (size_t)j0 * GD + 4 * idx);
    }
    __syncthreads();

    // warp w owns row jr = w; hoist its M row into registers
    float4 m0 = reinterpret_cast<const float4*>(s_M + warp * GD)[2 * lane];
    float4 m1 = reinterpret_cast<const float4*>(s_M + warp * GD)[2 * lane + 1];

    const float* crow = chg + (size_t)(j0 + warp) * GD;   // + b * N * GD per b

    // stream 32 b-rows; unroll 4 for MLP (8 LDG.128 in flight per warp)
#pragma unroll 4
    for (int b = 0; b < BB; b++) {
        const float4* c = reinterpret_cast<const float4*>(crow + (size_t)b * NTOK * GD);
        float4 c0 = c[2 * lane];
        float4 c1 = c[2 * lane + 1];
        float part = c0.x * m0.x + c0.y * m0.y + c0.z * m0.z + c0.w * m0.w
                   + c1.x * m1.x + c1.y * m1.y + c1.z * m1.z + c1.w * m1.w;
#pragma unroll
        for (int s = 16; s; s >>= 1) part += __shfl_xor_sync(0xffffffffu, part, s);
        if (lane == 0) s_sim[b * 9 + warp] = part;
    }
    __syncthreads();

    // ---- masked softmax over b (lane == b), warp w handles jr = w ----
    // Probe mask dtype from the first 1 KB (bool may arrive as u8 / i32 / f32).
    bool notint = false, notfloat = false;
    for (int i = lane; i < 256; i += 32) {
        unsigned int w = maskw[i];
        notint   |= (w > 1u);
        notfloat |= (w != 0u && w != 0x3f800000u);
    }
    notint   = __any_sync(0xffffffffu, notint);
    notfloat = __any_sync(0xffffffffu, notfloat);
    const int mode = notint ? (notfloat ? 1 : 2) : 0;   // 0=int32, 1=byte, 2=float32

    {
        const int jg = j0 + warp;
        float v = s_sim[lane * 9 + warp];
        bool mk;
        if (mode == 0)      mk = reinterpret_cast<const int*>(maskw)[(size_t)lane * NTOK + jg] != 0;
        else if (mode == 1) mk = reinterpret_cast<const unsigned char*>(maskw)[(size_t)lane * NTOK + jg] != 0;
        else                mk = reinterpret_cast<const float*>(maskw)[(size_t)lane * NTOK + jg] != 0.0f;
        v = mk ? v : -1e9f;
        float mx = v;
#pragma unroll
        for (int s = 16; s; s >>= 1) mx = fmaxf(mx, __shfl_xor_sync(0xffffffffu, mx, s));
        float ev = expf(v - mx);
        float sum = ev;
#pragma unroll
        for (int s = 16; s; s >>= 1) sum += __shfl_xor_sync(0xffffffffu, sum, s);
        out[(size_t)jg * BB + lane] = ev / sum;
    }
}

extern "C" void kernel_launch(void* const* d_in, const int* in_sizes, int n_in,
                              void* d_out, int out_size)
{
    const float*        chg  = (const float*)d_in[0];        // change_embeddings [B,N,256]
    const float*        edg  = (const float*)d_in[1];        // edges_embeddings  [N,512]
    const unsigned int* mask = (const unsigned int*)d_in[2]; // mask [B,N]
    const float*        Wq   = (const float*)d_in[3];        // [128,256]
    const float*        Wk   = (const float*)d_in[4];        // [128,512]
    float*              out  = (float*)d_out;                // [N,B]

    cudaFuncSetAttribute(cal_sim_gemm_kernel,
                         cudaFuncAttributeMaxDynamicSharedMemorySize, A_SMEM_BYTES);
    cal_sim_gemm_kernel<<<NTOK / JB, 256, A_SMEM_BYTES>>>(edg, Wq, Wk);
    cal_sim_stream_kernel<<<NTOK / JB2, 256>>>(chg, mask, out);
}